// round 8
// baseline (speedup 1.0000x reference)
#include <cuda_runtime.h>
#include <cuda_bf16.h>
#include <cstdint>

// Problem constants (fixed by the dataset)
#define Qn 20000
#define Gn 20000
#define Hn 32          // neighbors per query
#define Kn 15          // kernel points
#define Cn 128
#define On 128
#define KC (Kn * Cn)   // 1920

// Phase-2 GEMM tiling
#define BM 64
#define BN 128
#define BK 64
#define NCH (KC / BK)          // 30 chunks
#define LDT 144                // padded row stride in bytes (64 bf16 + 8 pad)
#define A_TILE_B (BM * LDT)    // 9216
#define B_TILE_B (BN * LDT)    // 18432
#define OFF_ALO  A_TILE_B
#define OFF_BHI  (2 * A_TILE_B)
#define OFF_BLO  (2 * A_TILE_B + B_TILE_B)
#define STAGE_B  (2 * A_TILE_B + 2 * B_TILE_B)   // 55296
#define SMEM_TOTAL (2 * STAGE_B)                  // 110592

// Scratch (device globals per harness rules)
__device__ __align__(256) __nv_bfloat16 g_Phi[(size_t)Qn * KC];
__device__ __align__(256) __nv_bfloat16 g_Plo[(size_t)Qn * KC];
__device__ __align__(256) __nv_bfloat16 g_Wthi[(size_t)On * KC];  // Wt[n][k]
__device__ __align__(256) __nv_bfloat16 g_Wtlo[(size_t)On * KC];

// ---------------------------------------------------------------------------
// PTX helpers (sm_80-era only: compile on base compute_103 target)
// ---------------------------------------------------------------------------
__device__ __forceinline__ uint32_t smem_u32(const void* p) {
    uint32_t a;
    asm("{ .reg .u64 t; cvta.to.shared.u64 t, %1; cvt.u32.u64 %0, t; }" : "=r"(a) : "l"(p));
    return a;
}
__device__ __forceinline__ void cp16(uint32_t dst, const void* src, int sz) {
    asm volatile("cp.async.cg.shared.global [%0], [%1], 16, %2;"
                 :: "r"(dst), "l"(src), "r"(sz) : "memory");
}
#define CP_COMMIT() asm volatile("cp.async.commit_group;" ::: "memory")
#define CP_WAIT(n)  asm volatile("cp.async.wait_group %0;" :: "n"(n) : "memory")

#define LDSM4(R, A)                                                          \
    asm volatile("ldmatrix.sync.aligned.m8n8.x4.shared.b16 {%0,%1,%2,%3}, [%4];" \
                 : "=r"((R)[0]), "=r"((R)[1]), "=r"((R)[2]), "=r"((R)[3]) : "r"(A))

#define MMA(C, A, B)                                                         \
    asm volatile("mma.sync.aligned.m16n8k16.row.col.f32.bf16.bf16.f32 "      \
                 "{%0,%1,%2,%3},{%4,%5,%6,%7},{%8,%9},{%0,%1,%2,%3};"        \
                 : "+f"((C)[0]), "+f"((C)[1]), "+f"((C)[2]), "+f"((C)[3])    \
                 : "r"((A)[0]), "r"((A)[1]), "r"((A)[2]), "r"((A)[3]),       \
                   "r"((B)[0]), "r"((B)[1]))

__device__ __forceinline__ void split_bf16(float v, __nv_bfloat16& hi, __nv_bfloat16& lo) {
    hi = __float2bfloat16(v);
    lo = __float2bfloat16(v - __bfloat162float(hi));
}

// ---------------------------------------------------------------------------
// Phase 1: P[q,k,c] = sum_h relu(1-||d||) * feat[nbr[q,h], c]  -> bf16 hi/lo
// One block per query; sparse h-bitmask contraction (~4.5% nonzero influences).
// ---------------------------------------------------------------------------
__global__ __launch_bounds__(128) void phase1_kernel(
    const float* __restrict__ qpts, const float* __restrict__ feats,
    const float* __restrict__ kpts, const int* __restrict__ nbr)
{
    int q = blockIdx.x;
    int t = threadIdx.x;

    __shared__ float    infl[Hn][Kn + 1];
    __shared__ int      idx[Hn];
    __shared__ unsigned kmask[Kn];
    __shared__ float    qp[3];
    __shared__ float    kp[Kn][3];

    if (t < Hn) idx[t] = nbr[q * Hn + t];
    if (t < 3)  qp[t] = qpts[q * 3 + t];
    if (t >= 64 && t < 64 + Kn * 3) {
        int u = t - 64;
        kp[u / 3][u % 3] = kpts[u];
    }
    __syncthreads();

    for (int p = t; p < Hn * Kn; p += 128) {
        int h = p / Kn, k = p % Kn;
        int j = idx[h];
        float dx = qpts[j * 3 + 0] - qp[0] - kp[k][0];
        float dy = qpts[j * 3 + 1] - qp[1] - kp[k][1];
        float dz = qpts[j * 3 + 2] - qp[2] - kp[k][2];
        float d  = sqrtf(fmaf(dx, dx, fmaf(dy, dy, dz * dz)));
        infl[h][k] = fmaxf(1.0f - d, 0.0f);
    }
    __syncthreads();

    if (t < Kn) {
        unsigned m = 0;
#pragma unroll
        for (int h = 0; h < Hn; h++)
            if (infl[h][t] > 0.0f) m |= (1u << h);
        kmask[t] = m;
    }
    __syncthreads();

    int c = t;
    size_t rowoff = (size_t)q * KC;
#pragma unroll
    for (int k = 0; k < Kn; k++) {
        float acc = 0.0f;
        unsigned m = kmask[k];
        while (m) {
            int h = __ffs(m) - 1;
            m &= m - 1;
            acc = fmaf(infl[h][k], feats[(size_t)idx[h] * Cn + c], acc);
        }
        __nv_bfloat16 hi, lo;
        split_bf16(acc, hi, lo);
        g_Phi[rowoff + k * Cn + c] = hi;
        g_Plo[rowoff + k * Cn + c] = lo;
    }
}

// ---------------------------------------------------------------------------
// W prep: Wt[n][k] = W[k][n] split into bf16 hi/lo. grid (60,4) block (32,8).
// ---------------------------------------------------------------------------
__global__ __launch_bounds__(256) void wprep_kernel(const float* __restrict__ W)
{
    __shared__ float tile[32][33];
    int k0 = blockIdx.x * 32, n0 = blockIdx.y * 32;
    int x = threadIdx.x;
#pragma unroll
    for (int r = threadIdx.y; r < 32; r += 8)
        tile[r][x] = W[(size_t)(k0 + r) * On + n0 + x];
    __syncthreads();
#pragma unroll
    for (int r = threadIdx.y; r < 32; r += 8) {
        float v = tile[x][r];
        __nv_bfloat16 hi, lo;
        split_bf16(v, hi, lo);
        size_t o = (size_t)(n0 + r) * KC + k0 + x;
        g_Wthi[o] = hi;
        g_Wtlo[o] = lo;
    }
}

// ---------------------------------------------------------------------------
// Phase 2: out = (Phi+Plo) @ (Wthi+Wtlo)^T via mma.sync bf16, 3 chains.
// CTA 64x128 tile, 4 warps (warp tile 32x64), BK=64, cp.async double buffer.
// ---------------------------------------------------------------------------
__device__ __forceinline__ void load_chunk(uint32_t sbase, int m0, int k0, int tid)
{
    // A hi/lo: 64 rows x 64 bf16  (512 x 16B per tile, 4 iters of 128 threads)
#pragma unroll
    for (int it = 0; it < 4; it++) {
        int idx = tid + it * 128;
        int r = idx >> 3, j = idx & 7;
        int gm = m0 + r;
        int ok = (gm < Qn);
        size_t go = (size_t)(ok ? gm : 0) * KC + k0 + j * 8;
        uint32_t so = sbase + r * LDT + j * 16;
        int sz = ok ? 16 : 0;
        cp16(so,           g_Phi + go, sz);
        cp16(so + OFF_ALO, g_Plo + go, sz);
    }
    // B hi/lo: 128 rows x 64 bf16 (1024 x 16B per tile, 8 iters)
#pragma unroll
    for (int it = 0; it < 8; it++) {
        int idx = tid + it * 128;
        int r = idx >> 3, j = idx & 7;
        size_t go = (size_t)r * KC + k0 + j * 8;
        uint32_t so = sbase + OFF_BHI + r * LDT + j * 16;
        cp16(so,                       g_Wthi + go, 16);
        cp16(so + (OFF_BLO - OFF_BHI), g_Wtlo + go, 16);
    }
}

__global__ __launch_bounds__(128) void phase2_mma(float* __restrict__ out)
{
    extern __shared__ char smem[];
    const uint32_t s0 = smem_u32(smem);
    const int tid = threadIdx.x;
    const int wid = tid >> 5;
    const int lid = tid & 31;
    const int m0 = blockIdx.x * BM;
    const int wm = wid & 1;        // m half (32 rows)
    const int wn = wid >> 1;       // n half (64 cols)

    float acc[2][8][4];
#pragma unroll
    for (int a = 0; a < 2; a++)
#pragma unroll
        for (int b = 0; b < 8; b++)
#pragma unroll
            for (int c = 0; c < 4; c++) acc[a][b][c] = 0.0f;

    load_chunk(s0, m0, 0, tid);
    CP_COMMIT();

    for (int i = 0; i < NCH; i++) {
        if (i + 1 < NCH) {
            load_chunk(s0 + ((i + 1) & 1) * STAGE_B, m0, (i + 1) * BK, tid);
            CP_COMMIT();
            CP_WAIT(1);
        } else {
            CP_WAIT(0);
        }
        __syncthreads();

        const uint32_t sb = s0 + (i & 1) * STAGE_B;
#pragma unroll
        for (int kst = 0; kst < 4; kst++) {
            const uint32_t kb = kst * 32 + (lid >> 4) * 16;   // byte offset within row
            uint32_t afh[2][4], afl[2][4];
#pragma unroll
            for (int mt = 0; mt < 2; mt++) {
                int row = wm * 32 + mt * 16 + (lid & 15);
                uint32_t off = row * LDT + kb;
                LDSM4(afh[mt], sb + off);
                LDSM4(afl[mt], sb + OFF_ALO + off);
            }
            uint32_t bfh[8][2], bfl[8][2];
#pragma unroll
            for (int p = 0; p < 4; p++) {
                int n = wn * 64 + p * 16 + (lid & 15);
                uint32_t off = n * LDT + kb;
                uint32_t r[4];
                LDSM4(r, sb + OFF_BHI + off);
                bfh[2 * p][0] = r[0]; bfh[2 * p][1] = r[2];
                bfh[2 * p + 1][0] = r[1]; bfh[2 * p + 1][1] = r[3];
                LDSM4(r, sb + OFF_BLO + off);
                bfl[2 * p][0] = r[0]; bfl[2 * p][1] = r[2];
                bfl[2 * p + 1][0] = r[1]; bfl[2 * p + 1][1] = r[3];
            }
#pragma unroll
            for (int mt = 0; mt < 2; mt++)
#pragma unroll
                for (int nt = 0; nt < 8; nt++) {
                    MMA(acc[mt][nt], afh[mt], bfh[nt]);
                    MMA(acc[mt][nt], afh[mt], bfl[nt]);
                    MMA(acc[mt][nt], afl[mt], bfh[nt]);
                }
        }
        __syncthreads();
    }

    // Epilogue
    int g = lid >> 2, tg = lid & 3;
#pragma unroll
    for (int mt = 0; mt < 2; mt++) {
        int r0 = m0 + wm * 32 + mt * 16 + g;
#pragma unroll
        for (int nt = 0; nt < 8; nt++) {
            int col = wn * 64 + nt * 8 + 2 * tg;
            if (r0 < Qn)
                *(float2*)&out[(size_t)r0 * On + col] =
                    make_float2(acc[mt][nt][0], acc[mt][nt][1]);
            if (r0 + 8 < Qn)
                *(float2*)&out[(size_t)(r0 + 8) * On + col] =
                    make_float2(acc[mt][nt][2], acc[mt][nt][3]);
        }
    }
}

// ---------------------------------------------------------------------------
// Launch
// ---------------------------------------------------------------------------
extern "C" void kernel_launch(void* const* d_in, const int* in_sizes, int n_in,
                              void* d_out, int out_size)
{
    const float* qpts  = 0;
    const float* feats = 0;
    const float* kpts  = 0;
    const float* W     = 0;
    const int*   nbr   = 0;

    for (int i = 0; i < n_in; i++) {
        int s = in_sizes[i];
        if      (s == Kn * 3)        { kpts  = (const float*)d_in[i]; }
        else if (s == Kn * Cn * On)  { W     = (const float*)d_in[i]; }
        else if (s == Qn * Hn)       { nbr   = (const int*)  d_in[i]; }
        else if (s == Gn * Cn)       { feats = (const float*)d_in[i]; }
        else if (s == Qn * 3)        { if (!qpts) qpts = (const float*)d_in[i]; }
    }
    if (!qpts || !feats || !kpts || !W || !nbr) {   // positional fallback
        qpts  = (const float*)d_in[0];
        feats = (const float*)d_in[2];
        kpts  = (const float*)d_in[3];
        W     = (const float*)d_in[4];
        nbr   = (const int*)  d_in[5];
    }
    float* out = (float*)d_out;

    static bool attr_set = false;
    if (!attr_set) {
        cudaFuncSetAttribute(phase2_mma,
                             cudaFuncAttributeMaxDynamicSharedMemorySize, SMEM_TOTAL);
        attr_set = true;
    }

    phase1_kernel<<<Qn, 128>>>(qpts, feats, kpts, nbr);
    wprep_kernel<<<dim3(KC / 32, On / 32), dim3(32, 8)>>>(W);
    phase2_mma<<<(Qn + BM - 1) / BM, 128, SMEM_TOTAL>>>(out);
}

// round 9
// speedup vs baseline: 1.5927x; 1.5927x over previous
#include <cuda_runtime.h>
#include <cuda_fp16.h>
#include <cstdint>

// Problem constants (fixed by the dataset)
#define Qn 20000
#define Gn 20000
#define Hn 32          // neighbors per query
#define Kn 15          // kernel points
#define Cn 128
#define On 128
#define KC (Kn * Cn)   // 1920

// Phase-2 GEMM tiling (fp16 single-chain)
#define BM 64
#define BN 128
#define BK 64
#define NCH (KC / BK)          // 30 chunks
#define LDT 144                // padded row stride in bytes (64 fp16 = 128B + 16 pad)
#define A_TILE_B (BM * LDT)    // 9216
#define B_TILE_B (BN * LDT)    // 18432
#define OFF_B    A_TILE_B
#define STAGE_B  (A_TILE_B + B_TILE_B)   // 27648
#define SMEM_TOTAL (2 * STAGE_B)          // 55296

// Scratch (device globals per harness rules)
__device__ __align__(256) __half g_P [(size_t)Qn * KC];   // 76.8 MB
__device__ __align__(256) __half g_Wt[(size_t)On * KC];   // Wt[n][k], 4.9 MB

// ---------------------------------------------------------------------------
// PTX helpers (sm_80-era only: compile on base compute_103 target)
// ---------------------------------------------------------------------------
__device__ __forceinline__ uint32_t smem_u32(const void* p) {
    uint32_t a;
    asm("{ .reg .u64 t; cvta.to.shared.u64 t, %1; cvt.u32.u64 %0, t; }" : "=r"(a) : "l"(p));
    return a;
}
__device__ __forceinline__ void cp16(uint32_t dst, const void* src, int sz) {
    asm volatile("cp.async.cg.shared.global [%0], [%1], 16, %2;"
                 :: "r"(dst), "l"(src), "r"(sz) : "memory");
}
#define CP_COMMIT() asm volatile("cp.async.commit_group;" ::: "memory")
#define CP_WAIT(n)  asm volatile("cp.async.wait_group %0;" :: "n"(n) : "memory")

#define LDSM4(R, A)                                                          \
    asm volatile("ldmatrix.sync.aligned.m8n8.x4.shared.b16 {%0,%1,%2,%3}, [%4];" \
                 : "=r"((R)[0]), "=r"((R)[1]), "=r"((R)[2]), "=r"((R)[3]) : "r"(A))

#define MMA(C, A, B)                                                         \
    asm volatile("mma.sync.aligned.m16n8k16.row.col.f32.f16.f16.f32 "        \
                 "{%0,%1,%2,%3},{%4,%5,%6,%7},{%8,%9},{%0,%1,%2,%3};"        \
                 : "+f"((C)[0]), "+f"((C)[1]), "+f"((C)[2]), "+f"((C)[3])    \
                 : "r"((A)[0]), "r"((A)[1]), "r"((A)[2]), "r"((A)[3]),       \
                   "r"((B)[0]), "r"((B)[1]))

// ---------------------------------------------------------------------------
// Phase 1: P[q,k,c] = sum_h relu(1-||d||) * feat[nbr[q,h], c]  -> fp16
// One block per query. Nonzero (h,k) terms (~4.5%) precompacted into per-k
// (weight, row-offset) lists so the 128-thread hot loop is pure LDS+LDG+FFMA.
// ---------------------------------------------------------------------------
__global__ __launch_bounds__(128) void phase1_kernel(
    const float* __restrict__ qpts, const float* __restrict__ feats,
    const float* __restrict__ kpts, const int* __restrict__ nbr)
{
    int q = blockIdx.x;
    int t = threadIdx.x;

    __shared__ float  infl[Hn][Kn + 1];
    __shared__ int    idx[Hn];
    __shared__ float2 terms[Kn][Hn];   // (weight, bitcast feat-row byte base idx)
    __shared__ int    cnt[Kn];
    __shared__ float  qp[3];
    __shared__ float  kp[Kn][3];

    if (t < Hn) idx[t] = nbr[q * Hn + t];
    if (t < 3)  qp[t] = qpts[q * 3 + t];
    if (t >= 64 && t < 64 + Kn * 3) {
        int u = t - 64;
        kp[u / 3][u % 3] = kpts[u];
    }
    __syncthreads();

    for (int p = t; p < Hn * Kn; p += 128) {
        int h = p / Kn, k = p % Kn;
        int j = idx[h];
        float dx = qpts[j * 3 + 0] - qp[0] - kp[k][0];
        float dy = qpts[j * 3 + 1] - qp[1] - kp[k][1];
        float dz = qpts[j * 3 + 2] - qp[2] - kp[k][2];
        float d  = sqrtf(fmaf(dx, dx, fmaf(dy, dy, dz * dz)));
        infl[h][k] = fmaxf(1.0f - d, 0.0f);
    }
    __syncthreads();

    // Compact nonzero (h) terms per k (threads 0..14)
    if (t < Kn) {
        int n = 0;
#pragma unroll
        for (int h = 0; h < Hn; h++) {
            float v = infl[h][t];
            if (v > 0.0f) {
                terms[t][n] = make_float2(v, __int_as_float(idx[h] * Cn));
                n++;
            }
        }
        cnt[t] = n;
    }
    __syncthreads();

    int c = t;
    size_t rowoff = (size_t)q * KC;
#pragma unroll
    for (int k = 0; k < Kn; k++) {
        float acc = 0.0f;
        int n = cnt[k];                       // warp-uniform
        for (int j = 0; j < n; j++) {
            float2 p = terms[k][j];
            acc = fmaf(p.x, feats[__float_as_int(p.y) + c], acc);
        }
        g_P[rowoff + k * Cn + c] = __float2half(acc);
    }
}

// ---------------------------------------------------------------------------
// W prep: Wt[n][k] = (fp16) W[k][n]. grid (60,4) block (32,8).
// ---------------------------------------------------------------------------
__global__ __launch_bounds__(256) void wprep_kernel(const float* __restrict__ W)
{
    __shared__ float tile[32][33];
    int k0 = blockIdx.x * 32, n0 = blockIdx.y * 32;
    int x = threadIdx.x;
#pragma unroll
    for (int r = threadIdx.y; r < 32; r += 8)
        tile[r][x] = W[(size_t)(k0 + r) * On + n0 + x];
    __syncthreads();
#pragma unroll
    for (int r = threadIdx.y; r < 32; r += 8)
        g_Wt[(size_t)(n0 + r) * KC + k0 + x] = __float2half(tile[x][r]);
}

// ---------------------------------------------------------------------------
// Phase 2: out = P @ Wt^T via mma.sync fp16, single chain, fp32 accum.
// CTA 64x128 tile, 4 warps (warp tile 32x64), BK=64, cp.async double buffer.
// ---------------------------------------------------------------------------
__device__ __forceinline__ void load_chunk(uint32_t sbase, int m0, int k0, int tid)
{
    // A: 64 rows x 64 fp16 (512 x 16B, 4 iters of 128 threads)
#pragma unroll
    for (int it = 0; it < 4; it++) {
        int idx = tid + it * 128;
        int r = idx >> 3, j = idx & 7;
        int gm = m0 + r;
        int ok = (gm < Qn);
        size_t go = (size_t)(ok ? gm : 0) * KC + k0 + j * 8;
        cp16(sbase + r * LDT + j * 16, g_P + go, ok ? 16 : 0);
    }
    // B: 128 rows x 64 fp16 (1024 x 16B, 8 iters)
#pragma unroll
    for (int it = 0; it < 8; it++) {
        int idx = tid + it * 128;
        int r = idx >> 3, j = idx & 7;
        cp16(sbase + OFF_B + r * LDT + j * 16, g_Wt + (size_t)r * KC + k0 + j * 8, 16);
    }
}

__global__ __launch_bounds__(128) void phase2_mma(float* __restrict__ out)
{
    extern __shared__ char smem[];
    const uint32_t s0 = smem_u32(smem);
    const int tid = threadIdx.x;
    const int wid = tid >> 5;
    const int lid = tid & 31;
    const int m0 = blockIdx.x * BM;
    const int wm = wid & 1;        // m half (32 rows)
    const int wn = wid >> 1;       // n half (64 cols)

    float acc[2][8][4];
#pragma unroll
    for (int a = 0; a < 2; a++)
#pragma unroll
        for (int b = 0; b < 8; b++)
#pragma unroll
            for (int c = 0; c < 4; c++) acc[a][b][c] = 0.0f;

    load_chunk(s0, m0, 0, tid);
    CP_COMMIT();

    for (int i = 0; i < NCH; i++) {
        if (i + 1 < NCH) {
            load_chunk(s0 + ((i + 1) & 1) * STAGE_B, m0, (i + 1) * BK, tid);
            CP_COMMIT();
            CP_WAIT(1);
        } else {
            CP_WAIT(0);
        }
        __syncthreads();

        const uint32_t sb = s0 + (i & 1) * STAGE_B;
#pragma unroll
        for (int kst = 0; kst < 4; kst++) {
            const uint32_t kb = kst * 32 + (lid >> 4) * 16;   // byte offset in row
            uint32_t af[2][4];
#pragma unroll
            for (int mt = 0; mt < 2; mt++) {
                int row = wm * 32 + mt * 16 + (lid & 15);
                LDSM4(af[mt], sb + row * LDT + kb);
            }
            uint32_t bf[8][2];
#pragma unroll
            for (int p = 0; p < 4; p++) {
                int n = wn * 64 + p * 16 + (lid & 15);
                uint32_t r[4];
                LDSM4(r, sb + OFF_B + n * LDT + kb);
                bf[2 * p][0] = r[0];     bf[2 * p][1] = r[2];
                bf[2 * p + 1][0] = r[1]; bf[2 * p + 1][1] = r[3];
            }
#pragma unroll
            for (int mt = 0; mt < 2; mt++)
#pragma unroll
                for (int nt = 0; nt < 8; nt++)
                    MMA(acc[mt][nt], af[mt], bf[nt]);
        }
        __syncthreads();
    }

    // Epilogue
    int g = lid >> 2, tg = lid & 3;
#pragma unroll
    for (int mt = 0; mt < 2; mt++) {
        int r0 = m0 + wm * 32 + mt * 16 + g;
#pragma unroll
        for (int nt = 0; nt < 8; nt++) {
            int col = wn * 64 + nt * 8 + 2 * tg;
            if (r0 < Qn)
                *(float2*)&out[(size_t)r0 * On + col] =
                    make_float2(acc[mt][nt][0], acc[mt][nt][1]);
            if (r0 + 8 < Qn)
                *(float2*)&out[(size_t)(r0 + 8) * On + col] =
                    make_float2(acc[mt][nt][2], acc[mt][nt][3]);
        }
    }
}

// ---------------------------------------------------------------------------
// Launch
// ---------------------------------------------------------------------------
extern "C" void kernel_launch(void* const* d_in, const int* in_sizes, int n_in,
                              void* d_out, int out_size)
{
    const float* qpts  = 0;
    const float* feats = 0;
    const float* kpts  = 0;
    const float* W     = 0;
    const int*   nbr   = 0;

    for (int i = 0; i < n_in; i++) {
        int s = in_sizes[i];
        if      (s == Kn * 3)        { kpts  = (const float*)d_in[i]; }
        else if (s == Kn * Cn * On)  { W     = (const float*)d_in[i]; }
        else if (s == Qn * Hn)       { nbr   = (const int*)  d_in[i]; }
        else if (s == Gn * Cn)       { feats = (const float*)d_in[i]; }
        else if (s == Qn * 3)        { if (!qpts) qpts = (const float*)d_in[i]; }
    }
    if (!qpts || !feats || !kpts || !W || !nbr) {   // positional fallback
        qpts  = (const float*)d_in[0];
        feats = (const float*)d_in[2];
        kpts  = (const float*)d_in[3];
        W     = (const float*)d_in[4];
        nbr   = (const int*)  d_in[5];
    }
    float* out = (float*)d_out;

    static bool attr_set = false;
    if (!attr_set) {
        cudaFuncSetAttribute(phase2_mma,
                             cudaFuncAttributeMaxDynamicSharedMemorySize, SMEM_TOTAL);
        attr_set = true;
    }

    phase1_kernel<<<Qn, 128>>>(qpts, feats, kpts, nbr);
    wprep_kernel<<<dim3(KC / 32, On / 32), dim3(32, 8)>>>(W);
    phase2_mma<<<(Qn + BM - 1) / BM, 128, SMEM_TOTAL>>>(out);
}

// round 10
// speedup vs baseline: 1.7933x; 1.1260x over previous
#include <cuda_runtime.h>
#include <cuda_fp16.h>
#include <cstdint>

// Problem constants (fixed by the dataset)
#define Qn 20000
#define Gn 20000
#define Hn 32          // neighbors per query
#define Kn 15          // kernel points
#define Cn 128
#define On 128
#define KC (Kn * Cn)   // 1920

// Phase-2 GEMM tiling (fp16 single-chain)
#define BM 64
#define BN 128
#define BK 64
#define NCH (KC / BK)          // 30 chunks
#define LDT 144                // padded row stride in bytes (64 fp16 = 128B + 16 pad)
#define A_TILE_B (BM * LDT)    // 9216
#define B_TILE_B (BN * LDT)    // 18432
#define OFF_B    A_TILE_B
#define STAGE_B  (A_TILE_B + B_TILE_B)   // 27648
#define SMEM_TOTAL (2 * STAGE_B)          // 55296

// Scratch (device globals per harness rules)
__device__ __align__(256) __half g_P [(size_t)Qn * KC];   // 76.8 MB
__device__ __align__(256) __half g_Wt[(size_t)On * KC];   // Wt[n][k], 4.9 MB

// ---------------------------------------------------------------------------
// PTX helpers (sm_80-era only: compile on base compute_103 target)
// ---------------------------------------------------------------------------
__device__ __forceinline__ uint32_t smem_u32(const void* p) {
    uint32_t a;
    asm("{ .reg .u64 t; cvta.to.shared.u64 t, %1; cvt.u32.u64 %0, t; }" : "=r"(a) : "l"(p));
    return a;
}
__device__ __forceinline__ void cp16(uint32_t dst, const void* src, int sz) {
    asm volatile("cp.async.cg.shared.global [%0], [%1], 16, %2;"
                 :: "r"(dst), "l"(src), "r"(sz) : "memory");
}
#define CP_COMMIT() asm volatile("cp.async.commit_group;" ::: "memory")
#define CP_WAIT(n)  asm volatile("cp.async.wait_group %0;" :: "n"(n) : "memory")

#define LDSM4(R, A)                                                          \
    asm volatile("ldmatrix.sync.aligned.m8n8.x4.shared.b16 {%0,%1,%2,%3}, [%4];" \
                 : "=r"((R)[0]), "=r"((R)[1]), "=r"((R)[2]), "=r"((R)[3]) : "r"(A))

#define MMA(C, A, B)                                                         \
    asm volatile("mma.sync.aligned.m16n8k16.row.col.f32.f16.f16.f32 "        \
                 "{%0,%1,%2,%3},{%4,%5,%6,%7},{%8,%9},{%0,%1,%2,%3};"        \
                 : "+f"((C)[0]), "+f"((C)[1]), "+f"((C)[2]), "+f"((C)[3])    \
                 : "r"((A)[0]), "r"((A)[1]), "r"((A)[2]), "r"((A)[3]),       \
                   "r"((B)[0]), "r"((B)[1]))

// ---------------------------------------------------------------------------
// Phase 1: P[q,k,c] = sum_h relu(1-||d||) * feat[nbr[q,h], c]  -> fp16
// Block = 2 queries x 64 threads. Per query:
//   stage 1: dq[h] = pt[nbr_h] - pt[q] precomputed once (96 LDG, not 1440)
//   stage 2: 480 influences, pure smem+FMA
//   stage 3: compact nonzero (weight, feat-row) term lists per k
//   stage 4: contraction, 2 channels/thread, float2 gathers, half2 stores
// g_P is bit-identical to the 1-channel/thread version (same fp32 fma order).
// ---------------------------------------------------------------------------
__global__ __launch_bounds__(128) void phase1_kernel(
    const float* __restrict__ qpts, const float* __restrict__ feats,
    const float* __restrict__ kpts, const int* __restrict__ nbr)
{
    const int grp = threadIdx.x >> 6;   // which query in the pair
    const int u   = threadIdx.x & 63;
    const int q   = blockIdx.x * 2 + grp;

    __shared__ float  infl[2][Hn][Kn + 1];
    __shared__ int    rowB[2][Hn];       // idx * Cn (premultiplied)
    __shared__ float  dq[2][Hn][3];
    __shared__ float2 terms[2][Kn][Hn];  // (weight, bitcast feat-row base)
    __shared__ int    cnt[2][Kn];
    __shared__ float  kp[Kn][3];

    if (threadIdx.x < Kn * 3)
        kp[threadIdx.x / 3][threadIdx.x % 3] = kpts[threadIdx.x];

    // Stage 1: neighbor deltas (32 threads per group; no inner dependency)
    if (u < Hn) {
        int j = nbr[q * Hn + u];
        rowB[grp][u] = j * Cn;
        dq[grp][u][0] = qpts[j * 3 + 0] - qpts[q * 3 + 0];
        dq[grp][u][1] = qpts[j * 3 + 1] - qpts[q * 3 + 1];
        dq[grp][u][2] = qpts[j * 3 + 2] - qpts[q * 3 + 2];
    }
    __syncthreads();

    // Stage 2: 480 influences per query over 64 threads (7.5 iters)
    for (int p = u; p < Hn * Kn; p += 64) {
        int h = p / Kn, k = p % Kn;
        float dx = dq[grp][h][0] - kp[k][0];
        float dy = dq[grp][h][1] - kp[k][1];
        float dz = dq[grp][h][2] - kp[k][2];
        float d  = sqrtf(fmaf(dx, dx, fmaf(dy, dy, dz * dz)));
        infl[grp][h][k] = fmaxf(1.0f - d, 0.0f);
    }
    __syncthreads();

    // Stage 3: compact nonzero h-terms per k (threads 0..14 of each group)
    if (u < Kn) {
        int n = 0;
#pragma unroll
        for (int h = 0; h < Hn; h++) {
            float v = infl[grp][h][u];
            if (v > 0.0f) {
                terms[grp][u][n] = make_float2(v, __int_as_float(rowB[grp][h]));
                n++;
            }
        }
        cnt[grp][u] = n;
    }
    __syncthreads();

    // Stage 4: contraction, channels c = 2u, 2u+1
    const int c = u * 2;
    size_t rowoff = (size_t)q * KC;
#pragma unroll
    for (int k = 0; k < Kn; k++) {
        float ax = 0.0f, ay = 0.0f;
        int n = cnt[grp][k];                 // group-uniform
        for (int j = 0; j < n; j++) {
            float2 p = terms[grp][k][j];
            float2 f = *(const float2*)&feats[__float_as_int(p.y) + c];
            ax = fmaf(p.x, f.x, ax);
            ay = fmaf(p.x, f.y, ay);
        }
        *(__half2*)&g_P[rowoff + k * Cn + c] = __floats2half2_rn(ax, ay);
    }
}

// ---------------------------------------------------------------------------
// W prep: Wt[n][k] = (fp16) W[k][n]. grid (60,4) block (32,8).
// ---------------------------------------------------------------------------
__global__ __launch_bounds__(256) void wprep_kernel(const float* __restrict__ W)
{
    __shared__ float tile[32][33];
    int k0 = blockIdx.x * 32, n0 = blockIdx.y * 32;
    int x = threadIdx.x;
#pragma unroll
    for (int r = threadIdx.y; r < 32; r += 8)
        tile[r][x] = W[(size_t)(k0 + r) * On + n0 + x];
    __syncthreads();
#pragma unroll
    for (int r = threadIdx.y; r < 32; r += 8)
        g_Wt[(size_t)(n0 + r) * KC + k0 + x] = __float2half(tile[x][r]);
}

// ---------------------------------------------------------------------------
// Phase 2: out = P @ Wt^T via mma.sync fp16, single chain, fp32 accum.
// CTA 64x128 tile, 4 warps (warp tile 32x64), BK=64, cp.async double buffer.
// ---------------------------------------------------------------------------
__device__ __forceinline__ void load_chunk(uint32_t sbase, int m0, int k0, int tid)
{
    // A: 64 rows x 64 fp16 (512 x 16B, 4 iters of 128 threads)
#pragma unroll
    for (int it = 0; it < 4; it++) {
        int idx = tid + it * 128;
        int r = idx >> 3, j = idx & 7;
        int gm = m0 + r;
        int ok = (gm < Qn);
        size_t go = (size_t)(ok ? gm : 0) * KC + k0 + j * 8;
        cp16(sbase + r * LDT + j * 16, g_P + go, ok ? 16 : 0);
    }
    // B: 128 rows x 64 fp16 (1024 x 16B, 8 iters)
#pragma unroll
    for (int it = 0; it < 8; it++) {
        int idx = tid + it * 128;
        int r = idx >> 3, j = idx & 7;
        cp16(sbase + OFF_B + r * LDT + j * 16, g_Wt + (size_t)r * KC + k0 + j * 8, 16);
    }
}

__global__ __launch_bounds__(128) void phase2_mma(float* __restrict__ out)
{
    extern __shared__ char smem[];
    const uint32_t s0 = smem_u32(smem);
    const int tid = threadIdx.x;
    const int wid = tid >> 5;
    const int lid = tid & 31;
    const int m0 = blockIdx.x * BM;
    const int wm = wid & 1;        // m half (32 rows)
    const int wn = wid >> 1;       // n half (64 cols)

    float acc[2][8][4];
#pragma unroll
    for (int a = 0; a < 2; a++)
#pragma unroll
        for (int b = 0; b < 8; b++)
#pragma unroll
            for (int c = 0; c < 4; c++) acc[a][b][c] = 0.0f;

    load_chunk(s0, m0, 0, tid);
    CP_COMMIT();

    for (int i = 0; i < NCH; i++) {
        if (i + 1 < NCH) {
            load_chunk(s0 + ((i + 1) & 1) * STAGE_B, m0, (i + 1) * BK, tid);
            CP_COMMIT();
            CP_WAIT(1);
        } else {
            CP_WAIT(0);
        }
        __syncthreads();

        const uint32_t sb = s0 + (i & 1) * STAGE_B;
#pragma unroll
        for (int kst = 0; kst < 4; kst++) {
            const uint32_t kb = kst * 32 + (lid >> 4) * 16;   // byte offset in row
            uint32_t af[2][4];
#pragma unroll
            for (int mt = 0; mt < 2; mt++) {
                int row = wm * 32 + mt * 16 + (lid & 15);
                LDSM4(af[mt], sb + row * LDT + kb);
            }
            uint32_t bf[8][2];
#pragma unroll
            for (int p = 0; p < 4; p++) {
                int n = wn * 64 + p * 16 + (lid & 15);
                uint32_t r[4];
                LDSM4(r, sb + OFF_B + n * LDT + kb);
                bf[2 * p][0] = r[0];     bf[2 * p][1] = r[2];
                bf[2 * p + 1][0] = r[1]; bf[2 * p + 1][1] = r[3];
            }
#pragma unroll
            for (int mt = 0; mt < 2; mt++)
#pragma unroll
                for (int nt = 0; nt < 8; nt++)
                    MMA(acc[mt][nt], af[mt], bf[nt]);
        }
        __syncthreads();
    }

    // Epilogue
    int g = lid >> 2, tg = lid & 3;
#pragma unroll
    for (int mt = 0; mt < 2; mt++) {
        int r0 = m0 + wm * 32 + mt * 16 + g;
#pragma unroll
        for (int nt = 0; nt < 8; nt++) {
            int col = wn * 64 + nt * 8 + 2 * tg;
            if (r0 < Qn)
                *(float2*)&out[(size_t)r0 * On + col] =
                    make_float2(acc[mt][nt][0], acc[mt][nt][1]);
            if (r0 + 8 < Qn)
                *(float2*)&out[(size_t)(r0 + 8) * On + col] =
                    make_float2(acc[mt][nt][2], acc[mt][nt][3]);
        }
    }
}

// ---------------------------------------------------------------------------
// Launch
// ---------------------------------------------------------------------------
extern "C" void kernel_launch(void* const* d_in, const int* in_sizes, int n_in,
                              void* d_out, int out_size)
{
    const float* qpts  = 0;
    const float* feats = 0;
    const float* kpts  = 0;
    const float* W     = 0;
    const int*   nbr   = 0;

    for (int i = 0; i < n_in; i++) {
        int s = in_sizes[i];
        if      (s == Kn * 3)        { kpts  = (const float*)d_in[i]; }
        else if (s == Kn * Cn * On)  { W     = (const float*)d_in[i]; }
        else if (s == Qn * Hn)       { nbr   = (const int*)  d_in[i]; }
        else if (s == Gn * Cn)       { feats = (const float*)d_in[i]; }
        else if (s == Qn * 3)        { if (!qpts) qpts = (const float*)d_in[i]; }
    }
    if (!qpts || !feats || !kpts || !W || !nbr) {   // positional fallback
        qpts  = (const float*)d_in[0];
        feats = (const float*)d_in[2];
        kpts  = (const float*)d_in[3];
        W     = (const float*)d_in[4];
        nbr   = (const int*)  d_in[5];
    }
    float* out = (float*)d_out;

    static bool attr_set = false;
    if (!attr_set) {
        cudaFuncSetAttribute(phase2_mma,
                             cudaFuncAttributeMaxDynamicSharedMemorySize, SMEM_TOTAL);
        attr_set = true;
    }

    phase1_kernel<<<Qn / 2, 128>>>(qpts, feats, kpts, nbr);
    wprep_kernel<<<dim3(KC / 32, On / 32), dim3(32, 8)>>>(W);
    phase2_mma<<<(Qn + BM - 1) / BM, 128, SMEM_TOTAL>>>(out);
}

// round 11
// speedup vs baseline: 1.9267x; 1.0744x over previous
#include <cuda_runtime.h>
#include <cuda_fp16.h>
#include <cstdint>

// Problem constants (fixed by the dataset)
#define Qn 20000
#define Gn 20000
#define Hn 32          // neighbors per query
#define Kn 15          // kernel points
#define Cn 128
#define On 128
#define KC (Kn * Cn)   // 1920

// Phase-2 GEMM tiling (fp16 single-chain)
#define BM 64
#define BN 128
#define BK 64
#define NCH (KC / BK)          // 30 chunks
#define LDT 144                // padded row stride in bytes (64 fp16 = 128B + 16 pad)
#define A_TILE_B (BM * LDT)    // 9216
#define B_TILE_B (BN * LDT)    // 18432
#define OFF_B    A_TILE_B
#define STAGE_B  (A_TILE_B + B_TILE_B)   // 27648
#define SMEM_TOTAL (2 * STAGE_B)          // 55296

// Scratch (device globals per harness rules)
__device__ __align__(256) __half g_P [(size_t)Qn * KC];   // 76.8 MB
__device__ __align__(256) __half g_Wt[(size_t)On * KC];   // Wt[n][k], 4.9 MB

// ---------------------------------------------------------------------------
// PTX helpers (sm_80-era only: compile on base compute_103 target)
// ---------------------------------------------------------------------------
__device__ __forceinline__ uint32_t smem_u32(const void* p) {
    uint32_t a;
    asm("{ .reg .u64 t; cvta.to.shared.u64 t, %1; cvt.u32.u64 %0, t; }" : "=r"(a) : "l"(p));
    return a;
}
__device__ __forceinline__ void cp16(uint32_t dst, const void* src, int sz) {
    asm volatile("cp.async.cg.shared.global [%0], [%1], 16, %2;"
                 :: "r"(dst), "l"(src), "r"(sz) : "memory");
}
#define CP_COMMIT() asm volatile("cp.async.commit_group;" ::: "memory")
#define CP_WAIT(n)  asm volatile("cp.async.wait_group %0;" :: "n"(n) : "memory")

#define LDSM4(R, A)                                                          \
    asm volatile("ldmatrix.sync.aligned.m8n8.x4.shared.b16 {%0,%1,%2,%3}, [%4];" \
                 : "=r"((R)[0]), "=r"((R)[1]), "=r"((R)[2]), "=r"((R)[3]) : "r"(A))

#define MMA(C, A, B)                                                         \
    asm volatile("mma.sync.aligned.m16n8k16.row.col.f32.f16.f16.f32 "        \
                 "{%0,%1,%2,%3},{%4,%5,%6,%7},{%8,%9},{%0,%1,%2,%3};"        \
                 : "+f"((C)[0]), "+f"((C)[1]), "+f"((C)[2]), "+f"((C)[3])    \
                 : "r"((A)[0]), "r"((A)[1]), "r"((A)[2]), "r"((A)[3]),       \
                   "r"((B)[0]), "r"((B)[1]))

// ---------------------------------------------------------------------------
// Phase 1: P[q,k,c] = sum_h relu(1-||d||) * feat[nbr[q,h], c]  -> fp16
// Block = 4 queries x 32 threads (1 warp per query).
//   stage 1: 128 threads load 128 neighbors; dq = pt[nbr]-pt[q]
//   stage 2: 4x480 influences, block-wide, pure smem+FMA
//   stage 3: per-k compaction of nonzero (weight, feat-row) terms
//   stage 4: contraction; 4 channels/thread, float4 gathers, 8B half stores
// Same per-(k,c) fp32 fma order as before -> g_P bit-identical.
// ---------------------------------------------------------------------------
__global__ __launch_bounds__(128) void phase1_kernel(
    const float* __restrict__ qpts, const float* __restrict__ feats,
    const float* __restrict__ kpts, const int* __restrict__ nbr)
{
    const int tid = threadIdx.x;
    const int grp = tid >> 5;           // query within block (warp id)
    const int u   = tid & 31;           // lane
    const int qb  = blockIdx.x * 4;

    __shared__ float  infl[4][Hn][Kn + 1];
    __shared__ int    rowB[4][Hn];       // idx * Cn (premultiplied)
    __shared__ float  dq[4][Hn][3];
    __shared__ float2 terms[4][Kn][Hn];  // (weight, bitcast feat-row base)
    __shared__ int    cnt[4][Kn];
    __shared__ float  kp[Kn][3];

    if (tid < Kn * 3)
        kp[tid / 3][tid % 3] = kpts[tid];

    // Stage 1: one neighbor per thread (128 = 4 queries x 32 h, coalesced)
    {
        int q = qb + grp;
        int j = nbr[q * Hn + u];
        rowB[grp][u] = j * Cn;
        dq[grp][u][0] = qpts[j * 3 + 0] - qpts[q * 3 + 0];
        dq[grp][u][1] = qpts[j * 3 + 1] - qpts[q * 3 + 1];
        dq[grp][u][2] = qpts[j * 3 + 2] - qpts[q * 3 + 2];
    }
    __syncthreads();

    // Stage 2: 4*480 = 1920 influences over 128 threads (15 iters)
#pragma unroll
    for (int it = 0; it < 15; it++) {
        int p  = tid + it * 128;
        int qq = p / (Hn * Kn);
        int r  = p % (Hn * Kn);
        int h  = r / Kn, k = r % Kn;
        float dx = dq[qq][h][0] - kp[k][0];
        float dy = dq[qq][h][1] - kp[k][1];
        float dz = dq[qq][h][2] - kp[k][2];
        float d  = sqrtf(fmaf(dx, dx, fmaf(dy, dy, dz * dz)));
        infl[qq][h][k] = fmaxf(1.0f - d, 0.0f);
    }
    __syncthreads();

    // Stage 3: compact nonzero h-terms per k (lanes 0..14 of each warp)
    if (u < Kn) {
        int n = 0;
#pragma unroll
        for (int h = 0; h < Hn; h++) {
            float v = infl[grp][h][u];
            if (v > 0.0f) {
                terms[grp][u][n] = make_float2(v, __int_as_float(rowB[grp][h]));
                n++;
            }
        }
        cnt[grp][u] = n;
    }
    __syncthreads();

    // Stage 4: contraction; thread owns channels c..c+3 of query qb+grp
    const int c = u * 4;
    size_t rowoff = (size_t)(qb + grp) * KC;
#pragma unroll
    for (int k = 0; k < Kn; k++) {
        float ax = 0.0f, ay = 0.0f, az = 0.0f, aw = 0.0f;
        int n = cnt[grp][k];                 // warp-uniform
        const float2* tl = terms[grp][k];
        for (int j = 0; j < n; j++) {
            float2 p = tl[j];
            float4 f = *(const float4*)&feats[__float_as_int(p.y) + c];
            ax = fmaf(p.x, f.x, ax);
            ay = fmaf(p.x, f.y, ay);
            az = fmaf(p.x, f.z, az);
            aw = fmaf(p.x, f.w, aw);
        }
        __half2 lo = __floats2half2_rn(ax, ay);
        __half2 hi = __floats2half2_rn(az, aw);
        *(uint2*)&g_P[rowoff + k * Cn + c] =
            make_uint2(*(uint32_t*)&lo, *(uint32_t*)&hi);
    }
}

// ---------------------------------------------------------------------------
// W prep: Wt[n][k] = (fp16) W[k][n]. grid (60,4) block (32,8).
// ---------------------------------------------------------------------------
__global__ __launch_bounds__(256) void wprep_kernel(const float* __restrict__ W)
{
    __shared__ float tile[32][33];
    int k0 = blockIdx.x * 32, n0 = blockIdx.y * 32;
    int x = threadIdx.x;
#pragma unroll
    for (int r = threadIdx.y; r < 32; r += 8)
        tile[r][x] = W[(size_t)(k0 + r) * On + n0 + x];
    __syncthreads();
#pragma unroll
    for (int r = threadIdx.y; r < 32; r += 8)
        g_Wt[(size_t)(n0 + r) * KC + k0 + x] = __float2half(tile[x][r]);
}

// ---------------------------------------------------------------------------
// Phase 2: out = P @ Wt^T via mma.sync fp16, single chain, fp32 accum.
// CTA 64x128 tile, 4 warps (warp tile 32x64), BK=64, cp.async double buffer.
// ---------------------------------------------------------------------------
__device__ __forceinline__ void load_chunk(uint32_t sbase, int m0, int k0, int tid)
{
    // A: 64 rows x 64 fp16 (512 x 16B, 4 iters of 128 threads)
#pragma unroll
    for (int it = 0; it < 4; it++) {
        int idx = tid + it * 128;
        int r = idx >> 3, j = idx & 7;
        int gm = m0 + r;
        int ok = (gm < Qn);
        size_t go = (size_t)(ok ? gm : 0) * KC + k0 + j * 8;
        cp16(sbase + r * LDT + j * 16, g_P + go, ok ? 16 : 0);
    }
    // B: 128 rows x 64 fp16 (1024 x 16B, 8 iters)
#pragma unroll
    for (int it = 0; it < 8; it++) {
        int idx = tid + it * 128;
        int r = idx >> 3, j = idx & 7;
        cp16(sbase + OFF_B + r * LDT + j * 16, g_Wt + (size_t)r * KC + k0 + j * 8, 16);
    }
}

__global__ __launch_bounds__(128) void phase2_mma(float* __restrict__ out)
{
    extern __shared__ char smem[];
    const uint32_t s0 = smem_u32(smem);
    const int tid = threadIdx.x;
    const int wid = tid >> 5;
    const int lid = tid & 31;
    const int m0 = blockIdx.x * BM;
    const int wm = wid & 1;        // m half (32 rows)
    const int wn = wid >> 1;       // n half (64 cols)

    float acc[2][8][4];
#pragma unroll
    for (int a = 0; a < 2; a++)
#pragma unroll
        for (int b = 0; b < 8; b++)
#pragma unroll
            for (int c = 0; c < 4; c++) acc[a][b][c] = 0.0f;

    load_chunk(s0, m0, 0, tid);
    CP_COMMIT();

    for (int i = 0; i < NCH; i++) {
        if (i + 1 < NCH) {
            load_chunk(s0 + ((i + 1) & 1) * STAGE_B, m0, (i + 1) * BK, tid);
            CP_COMMIT();
            CP_WAIT(1);
        } else {
            CP_WAIT(0);
        }
        __syncthreads();

        const uint32_t sb = s0 + (i & 1) * STAGE_B;
#pragma unroll
        for (int kst = 0; kst < 4; kst++) {
            const uint32_t kb = kst * 32 + (lid >> 4) * 16;   // byte offset in row
            uint32_t af[2][4];
#pragma unroll
            for (int mt = 0; mt < 2; mt++) {
                int row = wm * 32 + mt * 16 + (lid & 15);
                LDSM4(af[mt], sb + row * LDT + kb);
            }
            uint32_t bf[8][2];
#pragma unroll
            for (int p = 0; p < 4; p++) {
                int n = wn * 64 + p * 16 + (lid & 15);
                uint32_t r[4];
                LDSM4(r, sb + OFF_B + n * LDT + kb);
                bf[2 * p][0] = r[0];     bf[2 * p][1] = r[2];
                bf[2 * p + 1][0] = r[1]; bf[2 * p + 1][1] = r[3];
            }
#pragma unroll
            for (int mt = 0; mt < 2; mt++)
#pragma unroll
                for (int nt = 0; nt < 8; nt++)
                    MMA(acc[mt][nt], af[mt], bf[nt]);
        }
        __syncthreads();
    }

    // Epilogue
    int g = lid >> 2, tg = lid & 3;
#pragma unroll
    for (int mt = 0; mt < 2; mt++) {
        int r0 = m0 + wm * 32 + mt * 16 + g;
#pragma unroll
        for (int nt = 0; nt < 8; nt++) {
            int col = wn * 64 + nt * 8 + 2 * tg;
            if (r0 < Qn)
                *(float2*)&out[(size_t)r0 * On + col] =
                    make_float2(acc[mt][nt][0], acc[mt][nt][1]);
            if (r0 + 8 < Qn)
                *(float2*)&out[(size_t)(r0 + 8) * On + col] =
                    make_float2(acc[mt][nt][2], acc[mt][nt][3]);
        }
    }
}

// ---------------------------------------------------------------------------
// Launch
// ---------------------------------------------------------------------------
extern "C" void kernel_launch(void* const* d_in, const int* in_sizes, int n_in,
                              void* d_out, int out_size)
{
    const float* qpts  = 0;
    const float* feats = 0;
    const float* kpts  = 0;
    const float* W     = 0;
    const int*   nbr   = 0;

    for (int i = 0; i < n_in; i++) {
        int s = in_sizes[i];
        if      (s == Kn * 3)        { kpts  = (const float*)d_in[i]; }
        else if (s == Kn * Cn * On)  { W     = (const float*)d_in[i]; }
        else if (s == Qn * Hn)       { nbr   = (const int*)  d_in[i]; }
        else if (s == Gn * Cn)       { feats = (const float*)d_in[i]; }
        else if (s == Qn * 3)        { if (!qpts) qpts = (const float*)d_in[i]; }
    }
    if (!qpts || !feats || !kpts || !W || !nbr) {   // positional fallback
        qpts  = (const float*)d_in[0];
        feats = (const float*)d_in[2];
        kpts  = (const float*)d_in[3];
        W     = (const float*)d_in[4];
        nbr   = (const int*)  d_in[5];
    }
    float* out = (float*)d_out;

    static bool attr_set = false;
    if (!attr_set) {
        cudaFuncSetAttribute(phase2_mma,
                             cudaFuncAttributeMaxDynamicSharedMemorySize, SMEM_TOTAL);
        attr_set = true;
    }

    phase1_kernel<<<Qn / 4, 128>>>(qpts, feats, kpts, nbr);
    wprep_kernel<<<dim3(KC / 32, On / 32), dim3(32, 8)>>>(W);
    phase2_mma<<<(Qn + BM - 1) / BM, 128, SMEM_TOTAL>>>(out);
}